// round 16
// baseline (speedup 1.0000x reference)
#include <cuda_runtime.h>
#include <cuda_bf16.h>
#include <math.h>
#include <stdint.h>

// Problem constants
#define B_  32
#define N_  4096
#define C_  512
#define EPS_INV 10.0f          // 1/EPS_SINKHORN

#define THREADS1 256           // 8 warps
#define NWARPS (THREADS1 / 32)
#define BLOCKS_PER_B 18        // grid 576 = 18*32 (<= 592 resident slots, ONE wave)
#define WARPS_PER_B (BLOCKS_PER_B * NWARPS)   // 144 warps share one batch's 4096 rows

#define STAGES 3               // per-warp ring stages (8 warps x 3 x 2KB = 48KB exactly)
#define ROW_F4 (C_ / 4)        // 128 float4 = 2KB per row

// Per-batch accumulators (allocation-free rule: __device__ globals; zero-init
// at module load, re-zeroed by the finishing block for graph replay)
__device__ float        g_vec[B_ * C_];     // 64KB: REDG-accumulated weighted sums
__device__ float        g_E[B_];            // REDG-accumulated exp-sums
__device__ unsigned int g_cnt[B_];          // last-arrival counters

__device__ __forceinline__ void cp_async16(float4* smem_dst, const float4* gmem_src) {
    uint32_t s = (uint32_t)__cvta_generic_to_shared(smem_dst);
    asm volatile("cp.async.cg.shared.global [%0], [%1], 16;\n" :: "r"(s), "l"(gmem_src));
}
#define CP_COMMIT()  asm volatile("cp.async.commit_group;\n" ::: "memory")
#define CP_WAIT(n)   asm volatile("cp.async.wait_group %0;\n" :: "n"(n) : "memory")

// ---------------------------------------------------------------------------
// Combines the two best measured ingredients:
//  * R15's balanced layout: grid 576 (18 blocks/batch), warp-interleaved rows
//    -> per-SM placement imbalance only +2.8% (vs +15.6% at grid 512).
//  * R12's warp-private 3-stage cp.async rings: fetch fully decoupled from the
//    compute chain, zero __syncthreads in the main loop (best intrinsic
//    per-warp duty measured: ~80%). cp.async group state is per-thread and
//    each lane reads back exactly the float4s it copied -> warps free-run.
// Epilogue: per-block REDG flush into per-batch accumulators; the 18th block
// of each batch finalizes. Zero static smem (epilogue aliases the dead ring).
//
// Per row: e = exp(10*(cos_sim - 1)) (shift m=0 valid since cos_sim <= 1),
// accumulate (e/|v|)*v and e. Softmax Z folds out analytically:
//   obs = num / (E + 1e-6*S),  total_mass = E / S,  S = E + exp(-10*dustbin).
// ---------------------------------------------------------------------------
__global__ __launch_bounds__(THREADS1, 4)
void uot_fused(const float* __restrict__ prompt,
               const float* __restrict__ vfeats,
               const float* __restrict__ dustbin_param,
               float* __restrict__ out)
{
    extern __shared__ float4 s_mem[];        // 48KB dynamic, 0 static

    const int b    = blockIdx.x / BLOCKS_PER_B;
    const int jblk = blockIdx.x % BLOCKS_PER_B;
    const int tid  = threadIdx.x;
    const int wid  = tid >> 5;
    const int lane = tid & 31;
    const int wb   = jblk * NWARPS + wid;    // warp index within batch: 0..143

    // Warp wid's private ring
    float4* s_ring = s_mem + (size_t)wid * STAGES * ROW_F4;

    const float*  vb    = vfeats + (size_t)b * N_ * C_;
    const float4* gbase = (const float4*)vb;

    // ---- Prologue: prefetch this warp's first STAGES rows (ragged-safe) ----
    #pragma unroll
    for (int s = 0; s < STAGES; s++) {
        const int r = wb + s * WARPS_PER_B;
        if (r < N_) {
            const float4* src = gbase + (size_t)r * ROW_F4;
            float4* dst = s_ring + s * ROW_F4;
            #pragma unroll
            for (int k = 0; k < 4; k++)
                cp_async16(dst + lane + k * 32, src + lane + k * 32);
        }
        CP_COMMIT();                         // empty groups keep counts aligned
    }

    // ---- Prompt into registers + its norm (overlaps prologue fetches) ----
    float4 p[4];
    {
        const float4* pr = (const float4*)(prompt + (size_t)b * C_);
        float ss = 0.f;
        #pragma unroll
        for (int j = 0; j < 4; j++) {
            p[j] = __ldg(pr + j * 32 + lane);
            ss += p[j].x * p[j].x + p[j].y * p[j].y + p[j].z * p[j].z + p[j].w * p[j].w;
        }
        #pragma unroll
        for (int o = 16; o; o >>= 1) ss += __shfl_xor_sync(0xffffffffu, ss, o);
        float pinv = rsqrtf(fmaxf(ss, 1e-24f));
        #pragma unroll
        for (int j = 0; j < 4; j++) {        // pre-scale prompt by 1/|p|
            p[j].x *= pinv; p[j].y *= pinv; p[j].z *= pinv; p[j].w *= pinv;
        }
    }

    // ---- Main loop: warp-private, barrier-free ----
    float acc[16];
    #pragma unroll
    for (int i = 0; i < 16; i++) acc[i] = 0.f;
    float Eacc = 0.f;

    int t = 0;
    for (int r = wb; r < N_; r += WARPS_PER_B, t++) {
        CP_WAIT(STAGES - 1);                 // own oldest row landed

        const float4* rowp = s_ring + (t % STAGES) * ROW_F4;
        float4 v[4];
        float dpv = 0.f, dvv = 0.f;
        #pragma unroll
        for (int j = 0; j < 4; j++) v[j] = rowp[j * 32 + lane];  // own lanes' data
        #pragma unroll
        for (int j = 0; j < 4; j++) {
            dpv += v[j].x * p[j].x + v[j].y * p[j].y + v[j].z * p[j].z + v[j].w * p[j].w;
            dvv += v[j].x * v[j].x + v[j].y * v[j].y + v[j].z * v[j].z + v[j].w * v[j].w;
        }
        #pragma unroll
        for (int o = 16; o; o >>= 1) {       // interleaved butterflies overlap
            dpv += __shfl_xor_sync(0xffffffffu, dpv, o);
            dvv += __shfl_xor_sync(0xffffffffu, dvv, o);
        }
        float invn = rsqrtf(fmaxf(dvv, 1e-24f));
        float e    = __expf(EPS_INV * (dpv * invn - 1.0f));   // p already unit-norm
        float w    = e * invn;               // weight applied to the RAW row
        Eacc += e;
        #pragma unroll
        for (int j = 0; j < 4; j++) {
            acc[j * 4 + 0] += w * v[j].x;
            acc[j * 4 + 1] += w * v[j].y;
            acc[j * 4 + 2] += w * v[j].z;
            acc[j * 4 + 3] += w * v[j].w;
        }

        // Refill this stage with row r + STAGES*144 (commit always)
        const int rn = r + STAGES * WARPS_PER_B;
        if (rn < N_) {
            const float4* src = gbase + (size_t)rn * ROW_F4;
            float4* dst = s_ring + (t % STAGES) * ROW_F4;
            #pragma unroll
            for (int k = 0; k < 4; k++)
                cp_async16(dst + lane + k * 32, src + lane + k * 32);
        }
        CP_COMMIT();
    }

    // ---- Epilogue: drain, one barrier, reuse ring as scratch ----
    CP_WAIT(0);
    __syncthreads();                         // all warps done with their rings

    float* sacc  = (float*)s_mem;            // NWARPS*C_ floats = 16KB
    float* sEw   = sacc + NWARPS * C_;       // NWARPS floats
    int*   sLast = (int*)(sEw + NWARPS);     // 1 int

    float4* sa4 = (float4*)(sacc + wid * C_);
    #pragma unroll
    for (int j = 0; j < 4; j++)
        sa4[j * 32 + lane] = make_float4(acc[j*4+0], acc[j*4+1], acc[j*4+2], acc[j*4+3]);
    if (lane == 0) sEw[wid] = Eacc;
    __syncthreads();

    #pragma unroll
    for (int c = tid; c < C_; c += THREADS1) {   // 2 iterations
        float s = 0.f;
        #pragma unroll
        for (int w = 0; w < NWARPS; w++) s += sacc[w * C_ + c];
        atomicAdd(&g_vec[b * C_ + c], s);        // no return use -> REDG
    }
    if (tid == 0) {
        float s = 0.f;
        #pragma unroll
        for (int w = 0; w < NWARPS; w++) s += sEw[w];
        atomicAdd(&g_E[b], s);
    }

    // ---- Last-of-18 block per batch finalizes ----
    __threadfence();                         // release REDs
    __syncthreads();
    if (tid == 0) {
        unsigned int old = atomicAdd(&g_cnt[b], 1u);
        *sLast = (old == BLOCKS_PER_B - 1);
    }
    __syncthreads();
    if (!*sLast) return;
    __threadfence();                         // acquire others' REDs

    const float E    = g_E[b];               // no prior LDG of g_vec/g_E here: L1 clean
    const float ebin = __expf(-EPS_INV * dustbin_param[0]);
    const float S    = E + ebin;
    const float dinv = 1.0f / (E + 1e-6f * S);

    #pragma unroll
    for (int c = tid; c < C_; c += THREADS1) {
        float num = g_vec[b * C_ + c];
        out[b * C_ + c] = num * dinv;
        g_vec[b * C_ + c] = 0.f;             // re-arm for next graph replay
    }
    if (tid == 0) {
        out[B_ * C_ + b] = E / S;            // total_mass
        g_E[b] = 0.f;
        g_cnt[b] = 0u;
    }
}

// ---------------------------------------------------------------------------
extern "C" void kernel_launch(void* const* d_in, const int* in_sizes, int n_in,
                              void* d_out, int out_size)
{
    const float* prompt  = (const float*)d_in[0];   // (32,1,512)
    const float* vfeats  = (const float*)d_in[1];   // (32,4096,512)
    // d_in[2] = dustbin_token : unused by the reference computation
    const float* dparam  = (const float*)d_in[3];   // (1,)
    float* out = (float*)d_out;

    const int smem = NWARPS * STAGES * ROW_F4 * sizeof(float4);  // 49152B dynamic, 0 static
    uot_fused<<<B_ * BLOCKS_PER_B, THREADS1, smem>>>(prompt, vfeats, dparam, out);
}

// round 17
// speedup vs baseline: 1.1574x; 1.1574x over previous
#include <cuda_runtime.h>
#include <cuda_bf16.h>
#include <math.h>
#include <stdint.h>

// Problem constants
#define B_  32
#define N_  4096
#define C_  512
#define EPS_INV 10.0f          // 1/EPS_SINKHORN

#define THREADS1 256           // 8 warps
#define NWARPS (THREADS1 / 32)
#define BLOCKS_PER_B 18        // grid 576 = 18*32 (<= 592 resident slots, ONE wave)
#define WARPS_PER_B (BLOCKS_PER_B * NWARPS)   // 144 warps share one batch's 4096 rows
#define PF_DIST 4              // L2 prefetch distance in warp-iterations (~1200cy lead)

// Per-batch accumulators (allocation-free rule: __device__ globals; zero-init
// at module load, re-zeroed by the finishing block for graph replay)
__device__ float        g_vec[B_ * C_];     // 64KB: REDG-accumulated weighted sums
__device__ float        g_E[B_];            // REDG-accumulated exp-sums
__device__ unsigned int g_cnt[B_];          // last-arrival counters

// ---------------------------------------------------------------------------
// R15 (best: balanced grid 576 + register snapshot prefetch) + L2 prefetch:
// each warp issues prefetch.global.L2 for the row PF_DIST iterations ahead
// (one 128B line per lane 0..15, zero register/smem pipeline cost). The LDG
// then hits L2 (~250cy) instead of DRAM (~600cy), which the depth-1 register
// prefetch + ~300cy compute chain can fully hide.
//
// Per row: e = exp(10*(cos_sim - 1)) (shift m=0 valid since cos_sim <= 1),
// accumulate (e/|v|)*v and e. Softmax Z folds out analytically:
//   obs = num / (E + 1e-6*S),  total_mass = E / S,  S = E + exp(-10*dustbin).
// ---------------------------------------------------------------------------
__global__ __launch_bounds__(THREADS1, 4)
void uot_fused(const float* __restrict__ prompt,
               const float* __restrict__ vfeats,
               const float* __restrict__ dustbin_param,
               float* __restrict__ out)
{
    const int b    = blockIdx.x / BLOCKS_PER_B;
    const int jblk = blockIdx.x % BLOCKS_PER_B;
    const int tid  = threadIdx.x;
    const int wid  = tid >> 5;
    const int lane = tid & 31;
    const int wb   = jblk * NWARPS + wid;    // warp index within batch: 0..143

    __shared__ float sp[C_];                 // normalized prompt (2KB)
    __shared__ float sacc[NWARPS][C_];       // 16KB
    __shared__ float sEw[NWARPS];
    __shared__ float s_pinv;
    __shared__ int   sLast;

    // ---- Load prompt, compute norm, normalize IN SMEM ----
    float ss = 0.f;
    #pragma unroll
    for (int i = tid; i < C_; i += THREADS1) {
        float v = prompt[b * C_ + i];
        sp[i] = v;
        ss += v * v;
    }
    #pragma unroll
    for (int o = 16; o; o >>= 1) ss += __shfl_xor_sync(0xffffffffu, ss, o);
    if (lane == 0) sEw[wid] = ss;
    __syncthreads();
    if (tid == 0) {
        float t = 0.f;
        #pragma unroll
        for (int w = 0; w < NWARPS; w++) t += sEw[w];
        s_pinv = rsqrtf(fmaxf(t, 1e-24f));
    }
    __syncthreads();
    {
        const float pinv = s_pinv;
        #pragma unroll
        for (int i = tid; i < C_; i += THREADS1) sp[i] *= pinv;
    }
    __syncthreads();

    // ---- Main streaming loop: rows wb, wb+144, ... with snapshot prefetch ----
    float acc[16];
    #pragma unroll
    for (int i = 0; i < 16; i++) acc[i] = 0.f;
    float Eacc = 0.f;

    const float*  vb  = vfeats + (size_t)b * N_ * C_;
    const float4* pr4 = (const float4*)sp;

    float4 v[4];
    {   // prologue: first row register prefetch + L2 prefetch of the pipe-ahead rows
        const float4* row0 = (const float4*)(vb + (size_t)wb * C_);
        #pragma unroll
        for (int j = 0; j < 4; j++) v[j] = __ldcs(row0 + j * 32 + lane);
        #pragma unroll
        for (int d = 1; d <= PF_DIST; d++) {
            const int rp = wb + d * WARPS_PER_B;
            if (rp < N_ && lane < 16) {
                const char* pf = (const char*)(vb + (size_t)rp * C_) + lane * 128;
                asm volatile("prefetch.global.L2 [%0];" :: "l"(pf));
            }
        }
    }

    for (int r = wb; r < N_; r += WARPS_PER_B) {
        // Snapshot current row, immediately issue next row's loads
        float4 c[4];
        #pragma unroll
        for (int j = 0; j < 4; j++) c[j] = v[j];

        const int rn = r + WARPS_PER_B;
        if (rn < N_) {
            const float4* rown = (const float4*)(vb + (size_t)rn * C_);
            #pragma unroll
            for (int j = 0; j < 4; j++) v[j] = __ldcs(rown + j * 32 + lane);
        }

        // L2 prefetch the row PF_DIST iterations ahead (16 x 128B lines = 2KB)
        const int rp = r + (PF_DIST + 1) * WARPS_PER_B;
        if (rp < N_ && lane < 16) {
            const char* pf = (const char*)(vb + (size_t)rp * C_) + lane * 128;
            asm volatile("prefetch.global.L2 [%0];" :: "l"(pf));
        }

        // Reduce/exp chain on current row (overlaps next row's L2 latency)
        float dpv = 0.f, dvv = 0.f;
        #pragma unroll
        for (int j = 0; j < 4; j++) {
            float4 p4 = pr4[j * 32 + lane];
            dpv += c[j].x * p4.x + c[j].y * p4.y + c[j].z * p4.z + c[j].w * p4.w;
            dvv += c[j].x * c[j].x + c[j].y * c[j].y + c[j].z * c[j].z + c[j].w * c[j].w;
        }
        #pragma unroll
        for (int o = 16; o; o >>= 1) {       // interleaved butterflies overlap
            dpv += __shfl_xor_sync(0xffffffffu, dpv, o);
            dvv += __shfl_xor_sync(0xffffffffu, dvv, o);
        }
        float invn = rsqrtf(fmaxf(dvv, 1e-24f));
        float e    = __expf(EPS_INV * (dpv * invn - 1.0f));   // sp already unit-norm
        float w    = e * invn;               // weight applied to the RAW row
        Eacc += e;
        #pragma unroll
        for (int j = 0; j < 4; j++) {
            acc[j * 4 + 0] += w * c[j].x;
            acc[j * 4 + 1] += w * c[j].y;
            acc[j * 4 + 2] += w * c[j].z;
            acc[j * 4 + 3] += w * c[j].w;
        }
    }

    // ---- Cross-warp combine in smem, then one REDG flush per block ----
    float4* sa4 = (float4*)sacc[wid];
    #pragma unroll
    for (int j = 0; j < 4; j++)
        sa4[j * 32 + lane] = make_float4(acc[j*4+0], acc[j*4+1], acc[j*4+2], acc[j*4+3]);
    __syncthreads();
    if (lane == 0) sEw[wid] = Eacc;
    __syncthreads();

    #pragma unroll
    for (int c = tid; c < C_; c += THREADS1) {   // 2 iterations
        float s = 0.f;
        #pragma unroll
        for (int w = 0; w < NWARPS; w++) s += sacc[w][c];
        atomicAdd(&g_vec[b * C_ + c], s);        // no return use -> REDG
    }
    if (tid == 0) {
        float s = 0.f;
        #pragma unroll
        for (int w = 0; w < NWARPS; w++) s += sEw[w];
        atomicAdd(&g_E[b], s);
    }

    // ---- Last-of-18 block per batch finalizes ----
    __threadfence();                         // release REDs
    __syncthreads();
    if (tid == 0) {
        unsigned int old = atomicAdd(&g_cnt[b], 1u);
        sLast = (old == BLOCKS_PER_B - 1);
    }
    __syncthreads();
    if (!sLast) return;
    __threadfence();                         // acquire others' REDs

    const float E    = g_E[b];               // no prior LDG of g_vec/g_E here: L1 clean
    const float ebin = __expf(-EPS_INV * dustbin_param[0]);
    const float S    = E + ebin;
    const float dinv = 1.0f / (E + 1e-6f * S);

    #pragma unroll
    for (int c = tid; c < C_; c += THREADS1) {
        float num = g_vec[b * C_ + c];
        out[b * C_ + c] = num * dinv;
        g_vec[b * C_ + c] = 0.f;             // re-arm for next graph replay
    }
    if (tid == 0) {
        out[B_ * C_ + b] = E / S;            // total_mass
        g_E[b] = 0.f;
        g_cnt[b] = 0u;
    }
}

// ---------------------------------------------------------------------------
extern "C" void kernel_launch(void* const* d_in, const int* in_sizes, int n_in,
                              void* d_out, int out_size)
{
    const float* prompt  = (const float*)d_in[0];   // (32,1,512)
    const float* vfeats  = (const float*)d_in[1];   // (32,4096,512)
    // d_in[2] = dustbin_token : unused by the reference computation
    const float* dparam  = (const float*)d_in[3];   // (1,)
    float* out = (float*)d_out;

    uot_fused<<<B_ * BLOCKS_PER_B, THREADS1>>>(prompt, vfeats, dparam, out);
}